// round 1
// baseline (speedup 1.0000x reference)
#include <cuda_runtime.h>
#include <math.h>

#define N_ROUTES 7
#define PC_DIM   512
#define MC_DIM   128
#define KCLS     25
#define BSZ      4096
#define COLS     (KCLS * MC_DIM)        // 3200
#define VOTE_PER_B (N_ROUTES * COLS)    // 22400
#define PP_STRIDE (N_ROUTES * PC_DIM)   // 3584

// 367 MB fp32 scratch for the vote tensor [B][N][K][MC]
__device__ float g_vote[(size_t)BSZ * VOTE_PER_B];

// ---------------------------------------------------------------------------
// Kernel 1: vote GEMM (fp32). For each route n:
//   C[b, col] = sum_d P[b, n, d] * W[n, d, col],  col = m*128 + v
// Classic 128x128 tile, BK=8, 256 threads, 8x8 microtile per thread.
// ---------------------------------------------------------------------------
#define BM 128
#define BN 128
#define BKK 8

__global__ __launch_bounds__(256) void vote_gemm_kernel(
    const float* __restrict__ P, const float* __restrict__ W) {
    __shared__ float As[BKK][BM];
    __shared__ float Bs[BKK][BN];

    const int n  = blockIdx.z;
    const int bm = blockIdx.y * BM;
    const int bn = blockIdx.x * BN;

    const float* A  = P + (size_t)n * PC_DIM;           // row stride PP_STRIDE
    const float* Bw = W + (size_t)n * PC_DIM * COLS;    // row stride COLS
    float*       C  = g_vote + (size_t)n * COLS;        // row stride VOTE_PER_B

    const int tid = threadIdx.x;
    const int tx = tid & 15, ty = tid >> 4;

    float acc[8][8];
#pragma unroll
    for (int i = 0; i < 8; i++)
#pragma unroll
        for (int j = 0; j < 8; j++) acc[i][j] = 0.f;

    const int arow = tid >> 1, aq = tid & 1;   // A tile: 128 rows x 2 float4
    const int bk   = tid >> 5, bq = tid & 31;  // B tile: 8 k-rows x 32 float4

    for (int k0 = 0; k0 < PC_DIM; k0 += BKK) {
        float4 a = *(const float4*)(A + (size_t)(bm + arow) * PP_STRIDE + k0 + aq * 4);
        As[aq * 4 + 0][arow] = a.x;
        As[aq * 4 + 1][arow] = a.y;
        As[aq * 4 + 2][arow] = a.z;
        As[aq * 4 + 3][arow] = a.w;
        *(float4*)&Bs[bk][bq * 4] =
            *(const float4*)(Bw + (size_t)(k0 + bk) * COLS + bn + bq * 4);
        __syncthreads();

#pragma unroll
        for (int k = 0; k < BKK; k++) {
            float ar[8], br[8];
            *(float4*)&ar[0] = *(float4*)&As[k][ty * 8];
            *(float4*)&ar[4] = *(float4*)&As[k][ty * 8 + 4];
            *(float4*)&br[0] = *(float4*)&Bs[k][tx * 8];
            *(float4*)&br[4] = *(float4*)&Bs[k][tx * 8 + 4];
#pragma unroll
            for (int i = 0; i < 8; i++)
#pragma unroll
                for (int j = 0; j < 8; j++) acc[i][j] += ar[i] * br[j];
        }
        __syncthreads();
    }

#pragma unroll
    for (int i = 0; i < 8; i++) {
        float* crow = C + (size_t)(bm + ty * 8 + i) * VOTE_PER_B + bn + tx * 8;
        *(float4*)(crow)     = make_float4(acc[i][0], acc[i][1], acc[i][2], acc[i][3]);
        *(float4*)(crow + 4) = make_float4(acc[i][4], acc[i][5], acc[i][6], acc[i][7]);
    }
}

// ---------------------------------------------------------------------------
// Kernel 2: fused routing. One CTA per batch row; vote slice cached in smem.
// ---------------------------------------------------------------------------
#define OFF_VOTE  0
#define OFF_POSE  22400
#define OFF_COEF  25600
#define OFF_AGREE 25776
#define OFF_ACT   25952
#define OFF_GAMMA 25960
#define OFF_BETA  26088
#define SMEM_FLOATS 26216
#define SMEM_BYTES  (SMEM_FLOATS * 4)

__device__ __forceinline__ float warp_sum(float v) {
#pragma unroll
    for (int o = 16; o; o >>= 1) v += __shfl_xor_sync(0xffffffffu, v, o);
    return v;
}

// LayerNorm in place over each of the 25 rows of s_pose (128 dims each).
// One warp per row; warps take rows warp, warp+8, ...
__device__ __forceinline__ void layernorm_pose(float* s_pose, const float* s_gamma,
                                               const float* s_beta, int warp, int lane) {
    for (int m = warp; m < KCLS; m += 8) {
        float x[4];
        float s = 0.f;
#pragma unroll
        for (int j = 0; j < 4; j++) {
            x[j] = s_pose[m * MC_DIM + lane + 32 * j];
            s += x[j];
        }
        s = warp_sum(s);
        const float mu = s * (1.f / MC_DIM);
        float ss = 0.f;
#pragma unroll
        for (int j = 0; j < 4; j++) {
            float d = x[j] - mu;
            ss += d * d;
        }
        ss = warp_sum(ss);
        const float var = ss * (1.f / MC_DIM);
        const float ve = var + 1e-5f;
        float r = rsqrtf(ve);
        r = r * (1.5f - 0.5f * ve * r * r);  // Newton refine
#pragma unroll
        for (int j = 0; j < 4; j++) {
            int v = lane + 32 * j;
            s_pose[m * MC_DIM + v] = (x[j] - mu) * r * s_gamma[v] + s_beta[v];
        }
    }
}

__global__ __launch_bounds__(256) void routing_kernel(
    const float* __restrict__ prim_act,
    const float* __restrict__ ln_gamma, const float* __restrict__ ln_beta,
    const float* __restrict__ embedding, const float* __restrict__ bias,
    float* __restrict__ out_logits, float* __restrict__ out_act,
    float* __restrict__ out_coef) {
    extern __shared__ float sm[];
    float* s_vote  = sm + OFF_VOTE;
    float* s_pose  = sm + OFF_POSE;
    float* s_coef  = sm + OFF_COEF;
    float* s_agree = sm + OFF_AGREE;
    float* s_act   = sm + OFF_ACT;
    float* s_gamma = sm + OFF_GAMMA;
    float* s_beta  = sm + OFF_BETA;

    const int b    = blockIdx.x;
    const int tid  = threadIdx.x;
    const int lane = tid & 31;
    const int warp = tid >> 5;

    // Load vote slice for this batch row (22400 floats = 5600 float4)
    {
        const float4* src = (const float4*)(g_vote + (size_t)b * VOTE_PER_B);
        float4* dst = (float4*)s_vote;
        for (int i = tid; i < VOTE_PER_B / 4; i += 256) dst[i] = src[i];
    }
    if (tid < N_ROUTES) s_act[tid] = prim_act[(size_t)b * N_ROUTES + tid];
    if (tid < MC_DIM) {
        s_gamma[tid] = ln_gamma[tid];
        s_beta[tid]  = ln_beta[tid];
    }
    __syncthreads();

    // -------- iteration 0: uniform routing coefficients --------
    for (int i = tid; i < COLS; i += 256) {
        float a = 0.f;
#pragma unroll
        for (int nn = 0; nn < N_ROUTES; nn++)
            a += s_act[nn] * s_vote[nn * COLS + i];
        s_pose[i] = a * (1.f / 25.f);
    }
    __syncthreads();
    layernorm_pose(s_pose, s_gamma, s_beta, warp, lane);
    __syncthreads();

    // -------- iterations 1 and 2 --------
    const float scale = 0.08838834764831845f;  // 1/sqrt(128)
    for (int it = 1; it <= 2; it++) {
        // agree[n][m] = (vote[n][m][:] . pose[m][:]) * scale ; one warp per (n,m)
        for (int idx = warp; idx < N_ROUTES * KCLS; idx += 8) {
            int nn = idx / KCLS;
            int m  = idx - nn * KCLS;
            const float4 v = ((const float4*)(s_vote + nn * COLS + m * MC_DIM))[lane];
            const float4 p = ((const float4*)(s_pose + m * MC_DIM))[lane];
            float d = v.x * p.x + v.y * p.y + v.z * p.z + v.w * p.w;
            d = warp_sum(d);
            if (lane == 0) s_agree[idx] = d * scale;
        }
        __syncthreads();

        // softmax over m (25) per route n ; one thread per n
        if (tid < N_ROUTES) {
            float mx = -1e30f;
            for (int m = 0; m < KCLS; m++) mx = fmaxf(mx, s_agree[tid * KCLS + m]);
            float sum = 0.f;
            for (int m = 0; m < KCLS; m++) {
                float e = expf(s_agree[tid * KCLS + m] - mx);
                s_coef[tid * KCLS + m] = e;
                sum += e;
            }
            float inv = 1.f / sum;
            for (int m = 0; m < KCLS; m++) s_coef[tid * KCLS + m] *= inv;
        }
        __syncthreads();

        if (it == 2) {  // returned routing_coef is from the last iteration
            for (int i = tid; i < N_ROUTES * KCLS; i += 256)
                out_coef[(size_t)b * (N_ROUTES * KCLS) + i] = s_coef[i];
        }

        // pose[m][v] = sum_n coef[n][m] * act[n] * vote[n][m][v]
        for (int i = tid; i < COLS; i += 256) {
            int m = i >> 7;
            float a = 0.f;
#pragma unroll
            for (int nn = 0; nn < N_ROUTES; nn++)
                a += s_coef[nn * KCLS + m] * s_act[nn] * s_vote[nn * COLS + i];
            s_pose[i] = a;
        }
        __syncthreads();
        layernorm_pose(s_pose, s_gamma, s_beta, warp, lane);
        __syncthreads();
    }

    // -------- logits: pose[m][:] . embedding[m][:] + bias[m] --------
    for (int m = warp; m < KCLS; m += 8) {
        const float4 p = ((const float4*)(s_pose + m * MC_DIM))[lane];
        const float4 e = ((const float4*)(embedding + (size_t)m * MC_DIM))[lane];
        float d = p.x * e.x + p.y * e.y + p.z * e.z + p.w * e.w;
        d = warp_sum(d);
        if (lane == 0) out_logits[(size_t)b * KCLS + m] = d + bias[m];
    }

    // prim_act passthrough
    if (tid < N_ROUTES) out_act[(size_t)b * N_ROUTES + tid] = s_act[tid];
}

// ---------------------------------------------------------------------------
extern "C" void kernel_launch(void* const* d_in, const int* in_sizes, int n_in,
                              void* d_out, int out_size) {
    const float* prim_pose = (const float*)d_in[0];
    const float* prim_act  = (const float*)d_in[1];
    const float* w         = (const float*)d_in[2];
    const float* ln_gamma  = (const float*)d_in[3];
    const float* ln_beta   = (const float*)d_in[4];
    const float* embedding = (const float*)d_in[5];
    const float* bias      = (const float*)d_in[6];

    float* out        = (float*)d_out;
    float* out_logits = out;
    float* out_act    = out + (size_t)BSZ * KCLS;
    float* out_coef   = out_act + (size_t)BSZ * N_ROUTES;

    dim3 g(COLS / BN, BSZ / BM, N_ROUTES);  // (25, 32, 7)
    vote_gemm_kernel<<<g, 256>>>(prim_pose, w);

    cudaFuncSetAttribute(routing_kernel,
                         cudaFuncAttributeMaxDynamicSharedMemorySize, SMEM_BYTES);
    routing_kernel<<<BSZ, 256, SMEM_BYTES>>>(prim_act, ln_gamma, ln_beta,
                                             embedding, bias,
                                             out_logits, out_act, out_coef);
}

// round 3
// speedup vs baseline: 2.1273x; 2.1273x over previous
#include <cuda_runtime.h>
#include <cuda_bf16.h>
#include <stdint.h>
#include <math.h>

#define N_ROUTES 7
#define PC_DIM   512
#define MC_DIM   128
#define KCLS     25
#define BSZ      4096
#define COLS     (KCLS * MC_DIM)        // 3200
#define VOTE_PER_B (N_ROUTES * COLS)    // 22400
#define PP_STRIDE (N_ROUTES * PC_DIM)   // 3584

// ---------------------------------------------------------------------------
// Device scratch
// ---------------------------------------------------------------------------
__device__ float g_vote[(size_t)BSZ * VOTE_PER_B];                    // 367 MB
__device__ __nv_bfloat16 g_Phi[(size_t)BSZ * PP_STRIDE];
__device__ __nv_bfloat16 g_Plo[(size_t)BSZ * PP_STRIDE];
__device__ __nv_bfloat16 g_Whi[(size_t)N_ROUTES * COLS * PC_DIM];     // [n][col][d]
__device__ __nv_bfloat16 g_Wlo[(size_t)N_ROUTES * COLS * PC_DIM];

__device__ __forceinline__ uint32_t smem_to_u32(const void* p) {
    uint32_t a;
    asm("{ .reg .u64 t; cvta.to.shared.u64 t, %1; cvt.u32.u64 %0, t; }"
        : "=r"(a) : "l"(p));
    return a;
}

// ---------------------------------------------------------------------------
// Prep kernel 1: split prim_pose into bf16 hi/lo
// ---------------------------------------------------------------------------
__global__ __launch_bounds__(512) void prep_p_kernel(const float* __restrict__ P) {
    size_t i = (size_t)blockIdx.x * 512 + threadIdx.x;   // float4 index
    float4 x = ((const float4*)P)[i];
    __nv_bfloat16 h0 = __float2bfloat16(x.x);
    __nv_bfloat16 h1 = __float2bfloat16(x.y);
    __nv_bfloat16 h2 = __float2bfloat16(x.z);
    __nv_bfloat16 h3 = __float2bfloat16(x.w);
    __nv_bfloat162* dh = (__nv_bfloat162*)g_Phi;
    __nv_bfloat162* dl = (__nv_bfloat162*)g_Plo;
    dh[2 * i]     = __nv_bfloat162(h0, h1);
    dh[2 * i + 1] = __nv_bfloat162(h2, h3);
    dl[2 * i] = __nv_bfloat162(__float2bfloat16(x.x - __bfloat162float(h0)),
                               __float2bfloat16(x.y - __bfloat162float(h1)));
    dl[2 * i + 1] = __nv_bfloat162(__float2bfloat16(x.z - __bfloat162float(h2)),
                                   __float2bfloat16(x.w - __bfloat162float(h3)));
}

// ---------------------------------------------------------------------------
// Prep kernel 2: transpose+split W[n][d][col] -> Whi/Wlo [n][col][d]
// ---------------------------------------------------------------------------
__global__ __launch_bounds__(256) void prep_w_kernel(const float* __restrict__ W) {
    __shared__ float tile[32][33];
    const int n = blockIdx.z;
    const int c0 = blockIdx.x * 32;
    const int d0 = blockIdx.y * 32;
    const float* Wn = W + (size_t)n * PC_DIM * COLS;
#pragma unroll
    for (int j = 0; j < 4; j++) {
        int d = d0 + threadIdx.y + j * 8;
        tile[threadIdx.y + j * 8][threadIdx.x] = Wn[(size_t)d * COLS + c0 + threadIdx.x];
    }
    __syncthreads();
#pragma unroll
    for (int j = 0; j < 4; j++) {
        int col = c0 + threadIdx.y + j * 8;
        int d = d0 + threadIdx.x;
        float x = tile[threadIdx.x][threadIdx.y + j * 8];
        __nv_bfloat16 h = __float2bfloat16(x);
        size_t o = ((size_t)n * COLS + col) * PC_DIM + d;
        g_Whi[o] = h;
        g_Wlo[o] = __float2bfloat16(x - __bfloat162float(h));
    }
}

// ---------------------------------------------------------------------------
// Vote GEMM on legacy tensor cores (mma.sync bf16, fp32 accumulate).
// D = Ah*Bh + Ah*Bl + Al*Bh, per route n:
//   vote[b, col] = sum_d P[b,n,d] * W[n,d,col]
// CTA tile 128x128, K-chunk 32, double-buffered cp.async, 8 warps (4x2),
// warp tile 32x64. Rows padded to 80B in smem for conflict-free ldmatrix.
// ---------------------------------------------------------------------------
#define KCH 32
#define ROWB 80                 // smem bytes per row (64 data + 16 pad)
#define T_AH 0
#define T_AL (128 * ROWB)       // 10240
#define T_BH (2 * 128 * ROWB)
#define T_BL (3 * 128 * ROWB)
#define STG_BYTES (4 * 128 * ROWB)   // 40960
#define GEMM_SMEM (2 * STG_BYTES)    // 81920

#define CP_ASYNC(sa, ga) \
    asm volatile("cp.async.cg.shared.global [%0], [%1], 16;" :: "r"(sa), "l"(ga))
#define CP_COMMIT() asm volatile("cp.async.commit_group;" ::: "memory")
#define CP_WAIT1()  asm volatile("cp.async.wait_group 1;" ::: "memory")
#define CP_WAIT0()  asm volatile("cp.async.wait_group 0;" ::: "memory")

#define LDSM_X4(r0, r1, r2, r3, a) \
    asm volatile("ldmatrix.sync.aligned.m8n8.x4.shared.b16 {%0,%1,%2,%3}, [%4];" \
        : "=r"(r0), "=r"(r1), "=r"(r2), "=r"(r3) : "r"(a))

#define MMA_BF16(d, a, b0, b1) \
    asm volatile("mma.sync.aligned.m16n8k16.row.col.f32.bf16.bf16.f32 " \
        "{%0,%1,%2,%3}, {%4,%5,%6,%7}, {%8,%9}, {%0,%1,%2,%3};" \
        : "+f"((d)[0]), "+f"((d)[1]), "+f"((d)[2]), "+f"((d)[3]) \
        : "r"((a)[0]), "r"((a)[1]), "r"((a)[2]), "r"((a)[3]), "r"(b0), "r"(b1))

__global__ __launch_bounds__(256, 2) void vote_gemm_tc(void) {
    extern __shared__ char smem[];
    const uint32_t sb = smem_to_u32(smem);
    const int tid  = threadIdx.x;
    const int lane = tid & 31;
    const int warp = tid >> 5;
    const int wm   = warp & 3;          // 0..3 -> M offset wm*32
    const int wn   = warp >> 2;         // 0..1 -> N offset wn*64

    const int n  = blockIdx.z;
    const int bm = blockIdx.y * 128;
    const int bn = blockIdx.x * 128;

    // -------- cp.async thread mapping: 2048 16B-chunks/stage, 8 per thread ----
    // chunk id = p*256 + tid ; tensor = id>>9 ; row = (id&511)>>2 ; ch = id&3
    const __nv_bfloat16* gA[2] = {
        g_Phi + (size_t)bm * PP_STRIDE + (size_t)n * PC_DIM,
        g_Plo + (size_t)bm * PP_STRIDE + (size_t)n * PC_DIM };
    const __nv_bfloat16* gB[2] = {
        g_Whi + ((size_t)n * COLS + bn) * PC_DIM,
        g_Wlo + ((size_t)n * COLS + bn) * PC_DIM };

    float acc[2][8][4];
#pragma unroll
    for (int i = 0; i < 2; i++)
#pragma unroll
        for (int j = 0; j < 8; j++)
#pragma unroll
            for (int q = 0; q < 4; q++) acc[i][j][q] = 0.f;

    // ldmatrix per-lane base offsets (row = lane&15, chunk = lane>>4)
    const int lrow = lane & 15, lch = lane >> 4;
    const uint32_t a_off0 = (uint32_t)((wm * 32 + lrow) * ROWB + lch * 16);
    const uint32_t b_off0 = (uint32_t)((wn * 64 + lrow) * ROWB + lch * 16);

    // ---- issue one stage of cp.async ----
    auto issue_stage = [&](int c, int buf) {
        const int k0 = c * KCH;
        const uint32_t sbase = sb + buf * STG_BYTES;
#pragma unroll
        for (int p = 0; p < 8; p++) {
            int id  = p * 256 + tid;
            int t   = id >> 9;          // 0..3
            int rem = id & 511;
            int row = rem >> 2;
            int ch  = rem & 3;
            uint32_t sa = sbase + t * (128 * ROWB) + row * ROWB + ch * 16;
            const __nv_bfloat16* g;
            if (t < 2) g = gA[t] + (size_t)row * PP_STRIDE + k0 + ch * 8;
            else       g = gB[t - 2] + (size_t)row * PC_DIM + k0 + ch * 8;
            CP_ASYNC(sa, g);
        }
        CP_COMMIT();
    };

    issue_stage(0, 0);

    const int NC = PC_DIM / KCH;   // 16
    for (int c = 0; c < NC; c++) {
        if (c + 1 < NC) {
            issue_stage(c + 1, (c + 1) & 1);
            CP_WAIT1();
        } else {
            CP_WAIT0();
        }
        __syncthreads();

        const uint32_t sbase = sb + (c & 1) * STG_BYTES;
#pragma unroll
        for (int ks = 0; ks < 2; ks++) {
            // A fragments (hi and lo), 2 m16 tiles each
            uint32_t ah[2][4], al[2][4];
#pragma unroll
            for (int mt = 0; mt < 2; mt++) {
                uint32_t ao = a_off0 + mt * 16 * ROWB + ks * 32;
                LDSM_X4(ah[mt][0], ah[mt][1], ah[mt][2], ah[mt][3], sbase + T_AH + ao);
                LDSM_X4(al[mt][0], al[mt][1], al[mt][2], al[mt][3], sbase + T_AL + ao);
            }
#pragma unroll
            for (int g = 0; g < 4; g++) {
                uint32_t bo = b_off0 + g * 16 * ROWB + ks * 32;
                uint32_t bh[4], bl[4];
                LDSM_X4(bh[0], bh[1], bh[2], bh[3], sbase + T_BH + bo);
                LDSM_X4(bl[0], bl[1], bl[2], bl[3], sbase + T_BL + bo);
                // ntile0: {m0, m2}; ntile1: {m1, m3}
#pragma unroll
                for (int mt = 0; mt < 2; mt++) {
                    MMA_BF16(acc[mt][g * 2 + 0], ah[mt], bh[0], bh[2]);
                    MMA_BF16(acc[mt][g * 2 + 1], ah[mt], bh[1], bh[3]);
                    MMA_BF16(acc[mt][g * 2 + 0], ah[mt], bl[0], bl[2]);
                    MMA_BF16(acc[mt][g * 2 + 1], ah[mt], bl[1], bl[3]);
                    MMA_BF16(acc[mt][g * 2 + 0], al[mt], bh[0], bh[2]);
                    MMA_BF16(acc[mt][g * 2 + 1], al[mt], bh[1], bh[3]);
                }
            }
        }
        __syncthreads();
    }

    // -------- epilogue: direct fp32 stores --------
#pragma unroll
    for (int mt = 0; mt < 2; mt++) {
#pragma unroll
        for (int j = 0; j < 8; j++) {
            int g = j >> 1, nt = j & 1;
            int row = bm + wm * 32 + mt * 16 + (lane >> 2);
            int col = bn + wn * 64 + g * 16 + nt * 8 + (lane & 3) * 2;
            float* d0 = g_vote + (size_t)row * VOTE_PER_B + (size_t)n * COLS + col;
            float* d1 = d0 + (size_t)8 * VOTE_PER_B;
            *(float2*)d0 = make_float2(acc[mt][j][0], acc[mt][j][1]);
            *(float2*)d1 = make_float2(acc[mt][j][2], acc[mt][j][3]);
        }
    }
}

// ---------------------------------------------------------------------------
// Fused routing kernel (512 threads per batch row; vote cached in smem)
// ---------------------------------------------------------------------------
#define OFF_VOTE  0
#define OFF_POSE  22400
#define OFF_COEF  25600
#define OFF_AGREE 25776
#define OFF_ACT   25952
#define OFF_GAMMA 25960
#define OFF_BETA  26088
#define SMEM_FLOATS 26216
#define SMEM_BYTES  (SMEM_FLOATS * 4)

__device__ __forceinline__ float warp_sum(float v) {
#pragma unroll
    for (int o = 16; o; o >>= 1) v += __shfl_xor_sync(0xffffffffu, v, o);
    return v;
}

__device__ __forceinline__ void layernorm_pose(float* s_pose, const float* s_gamma,
                                               const float* s_beta, int warp, int lane) {
    for (int m = warp; m < KCLS; m += 16) {
        float x[4];
        float s = 0.f;
#pragma unroll
        for (int j = 0; j < 4; j++) {
            x[j] = s_pose[m * MC_DIM + lane + 32 * j];
            s += x[j];
        }
        s = warp_sum(s);
        const float mu = s * (1.f / MC_DIM);
        float ss = 0.f;
#pragma unroll
        for (int j = 0; j < 4; j++) {
            float d = x[j] - mu;
            ss += d * d;
        }
        ss = warp_sum(ss);
        const float ve = ss * (1.f / MC_DIM) + 1e-5f;
        float r = rsqrtf(ve);
        r = r * (1.5f - 0.5f * ve * r * r);
#pragma unroll
        for (int j = 0; j < 4; j++) {
            int v = lane + 32 * j;
            s_pose[m * MC_DIM + v] = (x[j] - mu) * r * s_gamma[v] + s_beta[v];
        }
    }
}

__global__ __launch_bounds__(512) void routing_kernel(
    const float* __restrict__ prim_act,
    const float* __restrict__ ln_gamma, const float* __restrict__ ln_beta,
    const float* __restrict__ embedding, const float* __restrict__ bias,
    float* __restrict__ out_logits, float* __restrict__ out_act,
    float* __restrict__ out_coef) {
    extern __shared__ float sm[];
    float* s_vote  = sm + OFF_VOTE;
    float* s_pose  = sm + OFF_POSE;
    float* s_coef  = sm + OFF_COEF;
    float* s_agree = sm + OFF_AGREE;
    float* s_act   = sm + OFF_ACT;
    float* s_gamma = sm + OFF_GAMMA;
    float* s_beta  = sm + OFF_BETA;

    const int b    = blockIdx.x;
    const int tid  = threadIdx.x;
    const int lane = tid & 31;
    const int warp = tid >> 5;

    {
        const float4* src = (const float4*)(g_vote + (size_t)b * VOTE_PER_B);
        float4* dst = (float4*)s_vote;
        for (int i = tid; i < VOTE_PER_B / 4; i += 512) dst[i] = src[i];
    }
    if (tid < N_ROUTES) s_act[tid] = prim_act[(size_t)b * N_ROUTES + tid];
    if (tid < MC_DIM) {
        s_gamma[tid] = ln_gamma[tid];
        s_beta[tid]  = ln_beta[tid];
    }
    __syncthreads();

    // -------- iteration 0: uniform coefficients --------
    for (int i = tid; i < COLS; i += 512) {
        float a = 0.f;
#pragma unroll
        for (int nn = 0; nn < N_ROUTES; nn++)
            a += s_act[nn] * s_vote[nn * COLS + i];
        s_pose[i] = a * (1.f / 25.f);
    }
    __syncthreads();
    layernorm_pose(s_pose, s_gamma, s_beta, warp, lane);
    __syncthreads();

    const float scale = 0.08838834764831845f;  // 1/sqrt(128)
    for (int it = 1; it <= 2; it++) {
        for (int idx = warp; idx < N_ROUTES * KCLS; idx += 16) {
            int nn = idx / KCLS;
            int m  = idx - nn * KCLS;
            const float4 v = ((const float4*)(s_vote + nn * COLS + m * MC_DIM))[lane];
            const float4 p = ((const float4*)(s_pose + m * MC_DIM))[lane];
            float d = v.x * p.x + v.y * p.y + v.z * p.z + v.w * p.w;
            d = warp_sum(d);
            if (lane == 0) s_agree[idx] = d * scale;
        }
        __syncthreads();

        if (tid < N_ROUTES) {
            float mx = -1e30f;
            for (int m = 0; m < KCLS; m++) mx = fmaxf(mx, s_agree[tid * KCLS + m]);
            float sum = 0.f;
            for (int m = 0; m < KCLS; m++) {
                float e = expf(s_agree[tid * KCLS + m] - mx);
                s_coef[tid * KCLS + m] = e;
                sum += e;
            }
            float inv = 1.f / sum;
            for (int m = 0; m < KCLS; m++) s_coef[tid * KCLS + m] *= inv;
        }
        __syncthreads();

        if (it == 2) {
            for (int i = tid; i < N_ROUTES * KCLS; i += 512)
                out_coef[(size_t)b * (N_ROUTES * KCLS) + i] = s_coef[i];
        }

        for (int i = tid; i < COLS; i += 512) {
            int m = i >> 7;
            float a = 0.f;
#pragma unroll
            for (int nn = 0; nn < N_ROUTES; nn++)
                a += s_coef[nn * KCLS + m] * s_act[nn] * s_vote[nn * COLS + i];
            s_pose[i] = a;
        }
        __syncthreads();
        layernorm_pose(s_pose, s_gamma, s_beta, warp, lane);
        __syncthreads();
    }

    for (int m = warp; m < KCLS; m += 16) {
        const float4 p = ((const float4*)(s_pose + m * MC_DIM))[lane];
        const float4 e = ((const float4*)(embedding + (size_t)m * MC_DIM))[lane];
        float d = p.x * e.x + p.y * e.y + p.z * e.z + p.w * e.w;
        d = warp_sum(d);
        if (lane == 0) out_logits[(size_t)b * KCLS + m] = d + bias[m];
    }
    if (tid < N_ROUTES) out_act[(size_t)b * N_ROUTES + tid] = s_act[tid];
}

// ---------------------------------------------------------------------------
extern "C" void kernel_launch(void* const* d_in, const int* in_sizes, int n_in,
                              void* d_out, int out_size) {
    const float* prim_pose = (const float*)d_in[0];
    const float* prim_act  = (const float*)d_in[1];
    const float* w         = (const float*)d_in[2];
    const float* ln_gamma  = (const float*)d_in[3];
    const float* ln_beta   = (const float*)d_in[4];
    const float* embedding = (const float*)d_in[5];
    const float* bias      = (const float*)d_in[6];

    float* out        = (float*)d_out;
    float* out_logits = out;
    float* out_act    = out + (size_t)BSZ * KCLS;
    float* out_coef   = out_act + (size_t)BSZ * N_ROUTES;

    prep_p_kernel<<<(BSZ * PP_STRIDE) / 4 / 512, 512>>>(prim_pose);
    prep_w_kernel<<<dim3(COLS / 32, PC_DIM / 32, N_ROUTES), dim3(32, 8)>>>(w);

    cudaFuncSetAttribute(vote_gemm_tc,
                         cudaFuncAttributeMaxDynamicSharedMemorySize, GEMM_SMEM);
    dim3 g(COLS / 128, BSZ / 128, N_ROUTES);   // (25, 32, 7)
    vote_gemm_tc<<<g, 256, GEMM_SMEM>>>();

    cudaFuncSetAttribute(routing_kernel,
                         cudaFuncAttributeMaxDynamicSharedMemorySize, SMEM_BYTES);
    routing_kernel<<<BSZ, 512, SMEM_BYTES>>>(prim_act, ln_gamma, ln_beta,
                                             embedding, bias,
                                             out_logits, out_act, out_coef);
}